// round 8
// baseline (speedup 1.0000x reference)
#include <cuda_runtime.h>
#include <cuda_fp16.h>
#include <cstdint>
#include <math.h>

// ---------------- problem dims ----------------
#define BATCH 8
#define CCH   512
#define NQ    4096
#define TLEN  256
#define CDIM  768
#define HID   512
#define NHEAD 8
#define DHEAD 64

// ---------------- scratch ----------------
__device__ __half g_xh  [(long)BATCH * CCH * NQ];
__device__ __half g_ctxh[(long)BATCH * TLEN * CDIM];
__device__ __half g_Wqh [HID * CCH];
__device__ __half g_Wkvh[2 * HID * CDIM];
__device__ __half g_Wouth[CCH * HID];
__device__ __half g_q   [(long)BATCH * HID * NQ];        // [b][o][i]
__device__ __half g_kv  [(long)BATCH * 2 * HID * TLEN];  // [b][o][t]
__device__ __half g_out [(long)BATCH * NQ * HID];        // [b][i][hd]

__device__ __forceinline__ uint32_t smem_u32(const void* p) {
    uint32_t a;
    asm("{ .reg .u64 t; cvta.to.shared.u64 t, %1; cvt.u32.u64 %0, t; }" : "=r"(a) : "l"(p));
    return a;
}
__device__ __forceinline__ uint32_t h2(float a, float b) {
    __half2 h = __floats2half2_rn(a, b);
    return *(uint32_t*)&h;
}
__device__ __forceinline__ void cpa16(uint32_t dst, const void* src) {
    asm volatile("cp.async.cg.shared.global [%0], [%1], 16;" :: "r"(dst), "l"(src));
}
#define CP_COMMIT() asm volatile("cp.async.commit_group;" ::: "memory")
template<int N> __device__ __forceinline__ void cp_wait() {
    asm volatile("cp.async.wait_group %0;" :: "n"(N) : "memory");
}
__device__ __forceinline__ void ldsm4(uint32_t* r, uint32_t addr) {
    asm volatile("ldmatrix.sync.aligned.m8n8.x4.shared.b16 {%0,%1,%2,%3}, [%4];"
                 : "=r"(r[0]), "=r"(r[1]), "=r"(r[2]), "=r"(r[3]) : "r"(addr));
}
__device__ __forceinline__ void ldsm4t(uint32_t* r, uint32_t addr) {
    asm volatile("ldmatrix.sync.aligned.m8n8.x4.trans.shared.b16 {%0,%1,%2,%3}, [%4];"
                 : "=r"(r[0]), "=r"(r[1]), "=r"(r[2]), "=r"(r[3]) : "r"(addr));
}
__device__ __forceinline__ void mma_f16(float* d, const uint32_t* a, const uint32_t* b) {
    asm volatile(
        "mma.sync.aligned.m16n8k16.row.col.f32.f16.f16.f32 "
        "{%0,%1,%2,%3}, {%4,%5,%6,%7}, {%8,%9}, {%0,%1,%2,%3};"
        : "+f"(d[0]), "+f"(d[1]), "+f"(d[2]), "+f"(d[3])
        : "r"(a[0]), "r"(a[1]), "r"(a[2]), "r"(a[3]), "r"(b[0]), "r"(b[1]));
}

// ---------------- fp32 -> fp16 conversion ----------------
__global__ __launch_bounds__(256) void f2h_kernel(
    const float4* __restrict__ in, uint2* __restrict__ out, int n4)
{
    int i = blockIdx.x * 256 + threadIdx.x;
    if (i < n4) {
        float4 v = in[i];
        out[i] = make_uint2(h2(v.x, v.y), h2(v.z, v.w));
    }
}

// =====================================================================
// fp16 mma GEMM, CTA tile 256x128, warp tile 64x64 (4x2 warps), BK=32,
// 3-stage cp.async, 2 CTAs/SM.
//   C[z][m][n] = alpha * A[m][k] * B(k,n) (+ bias[m])
// A[m][k] k-contig. BDIR=1: B[n][k] k-contig. BDIR=0: B[k][n] n-contig.
// =====================================================================
template<int BDIR, typename CT>
__global__ __launch_bounds__(256, 2) void hgemm(
    const __half* __restrict__ A, const __half* __restrict__ B,
    CT* __restrict__ C, const float* __restrict__ bias,
    int lda, int ldb, int ldc, int kTotal,
    long sB1, long sC1, float alpha)
{
    constexpr int BM = 256, BN = 128, BK = 32;
    constexpr int AS = BK + 8;                      // 40 halves
    constexpr int BS = BDIR ? (BK + 8) : (BN + 8);  // 40 or 136
    constexpr int BROWS = BDIR ? BN : BK;
    constexpr int ASTG = BM * AS;
    constexpr int BSTG = BROWS * BS;

    extern __shared__ __half sm[];
    __half* Asm = sm;
    __half* Bsm = sm + 3 * ASTG;

    const int z = blockIdx.z;
    B += (long)z * sB1;
    C += (long)z * sC1;

    const int tid = threadIdx.x;
    const int wid = tid >> 5, lane = tid & 31;
    const int wm = wid & 3, wn = wid >> 2;       // 4 x 2 warp grid
    const int g = lane >> 2, t4 = lane & 3;
    const int l8 = lane & 7, l16 = lane & 15;
    const int lhi8 = (lane >> 4) << 3;
    const int lq8 = ((lane >> 3) & 1) << 3;

    const int m0 = blockIdx.y * BM;
    const int n0 = blockIdx.x * BN;
    const int mb = wm * 64, nb = wn * 64;

    const uint32_t Aaddr = smem_u32(Asm);
    const uint32_t Baddr = smem_u32(Bsm);

    float acc[4][8][4];
    #pragma unroll
    for (int i = 0; i < 4; i++)
        #pragma unroll
        for (int j = 0; j < 8; j++)
            #pragma unroll
            for (int r = 0; r < 4; r++) acc[i][j][r] = 0.0f;

    auto LOADS = [&](int s, int k0) {
        uint32_t ab = Aaddr + s * (ASTG * 2);
        uint32_t bb = Baddr + s * (BSTG * 2);
        #pragma unroll
        for (int r = 0; r < 4; r++) {
            int f = r * 256 + tid;
            int k8 = f & 3, m = f >> 2;
            cpa16(ab + (m * AS + k8 * 8) * 2, A + (long)(m0 + m) * lda + k0 + k8 * 8);
        }
        #pragma unroll
        for (int r = 0; r < 2; r++) {
            int f = r * 256 + tid;
            if (BDIR) {
                int k8 = f & 3, n = f >> 2;
                cpa16(bb + (n * BS + k8 * 8) * 2, B + (long)(n0 + n) * ldb + k0 + k8 * 8);
            } else {
                int n8 = f & 15, kk = f >> 4;
                cpa16(bb + (kk * BS + n8 * 8) * 2, B + (long)(k0 + kk) * ldb + n0 + n8 * 8);
            }
        }
    };
    auto COMPUTE = [&](int s) {
        const uint32_t ab = Aaddr + s * (ASTG * 2);
        const uint32_t bb = Baddr + s * (BSTG * 2);
        #pragma unroll
        for (int ks = 0; ks < 2; ks++) {
            const int kof = ks * 16;
            uint32_t a[4][4];
            #pragma unroll
            for (int mt = 0; mt < 4; mt++)
                ldsm4(a[mt], ab + ((mb + mt * 16 + l16) * AS + kof + lhi8) * 2);
            #pragma unroll
            for (int np = 0; np < 4; np++) {
                uint32_t b[4];
                if (BDIR)
                    ldsm4(b, bb + ((nb + np * 16 + lhi8 + l8) * BS + kof + lq8) * 2);
                else
                    ldsm4t(b, bb + ((kof + l16) * BS + nb + np * 16 + lhi8) * 2);
                #pragma unroll
                for (int mt = 0; mt < 4; mt++) {
                    mma_f16(acc[mt][np * 2],     a[mt], b);
                    mma_f16(acc[mt][np * 2 + 1], a[mt], b + 2);
                }
            }
        }
    };

    const int niter = kTotal / BK;
    LOADS(0, 0);
    CP_COMMIT();
    LOADS(1, BK);
    CP_COMMIT();
    cp_wait<1>();
    __syncthreads();

    for (int it = 0; it < niter; it++) {
        COMPUTE(it % 3);
        if (it + 2 < niter) {
            LOADS((it + 2) % 3, (it + 2) * BK);
            CP_COMMIT();
            cp_wait<1>();
        } else if (it + 1 < niter) {
            cp_wait<0>();
        }
        if (it + 1 < niter) __syncthreads();
    }

    #pragma unroll
    for (int mt = 0; mt < 4; mt++) {
        int m = m0 + mb + mt * 16 + g;
        float bv0 = bias ? bias[m] : 0.0f;
        float bv1 = bias ? bias[m + 8] : 0.0f;
        #pragma unroll
        for (int nt = 0; nt < 8; nt++) {
            int n = n0 + nb + nt * 8 + t4 * 2;
            if (sizeof(CT) == 4) {
                *(float2*)((float*)C + (long)m * ldc + n) =
                    make_float2(acc[mt][nt][0] * alpha + bv0, acc[mt][nt][1] * alpha + bv0);
                *(float2*)((float*)C + (long)(m + 8) * ldc + n) =
                    make_float2(acc[mt][nt][2] * alpha + bv1, acc[mt][nt][3] * alpha + bv1);
            } else {
                *(uint32_t*)((__half*)C + (long)m * ldc + n) =
                    h2(acc[mt][nt][0] * alpha + bv0, acc[mt][nt][1] * alpha + bv0);
                *(uint32_t*)((__half*)C + (long)(m + 8) * ldc + n) =
                    h2(acc[mt][nt][2] * alpha + bv1, acc[mt][nt][3] * alpha + bv1);
            }
        }
    }
}

// =====================================================================
// Fused attention (fp16 in/out): per CTA = (b,h) x 128-query tile.
// (unchanged from the 256.7us kernel)
// =====================================================================
#define QS 136
#define KS 264
#define VS 264
#define PS 264
#define OQ 0
#define OKk (OQ + 64 * QS)
#define OV  (OKk + 64 * KS)
#define OP  (OV + 64 * VS)
#define FH_TOTAL (OP + 128 * PS)
#define RED_BYTES 2048
#define FSM_BYTES (FH_TOTAL * 2 + RED_BYTES)

__global__ __launch_bounds__(256, 1) void fused_attn(
    const __half* __restrict__ q, const __half* __restrict__ kv,
    __half* __restrict__ out)
{
    extern __shared__ __align__(16) char smraw[];
    __half* sh = (__half*)smraw;
    float* red = (float*)(smraw + FH_TOTAL * 2);

    const int z = blockIdx.y;
    const int b = z >> 3, h = z & 7;
    const int i0 = blockIdx.x * 128;
    const int tid = threadIdx.x;
    const int wid = tid >> 5, lane = tid & 31;
    const int wm = wid & 3, wn = wid >> 2;
    const int g = lane >> 2, t4 = lane & 3;
    const int l8 = lane & 7, l16 = lane & 15;
    const int lhi8 = (lane >> 4) << 3;
    const int lq8 = ((lane >> 3) & 1) << 3;

    const __half* qp = q + (long)(b * HID + h * DHEAD) * NQ;
    const __half* kp = kv + (long)(b * 2 * HID + h * DHEAD) * TLEN;
    const __half* vp = kp + (long)HID * TLEN;

    const uint32_t sbase = smem_u32(sh);

    #pragma unroll
    for (int r = 0; r < 4; r++) {
        int f = r * 256 + tid;
        int i8 = f & 15, d = f >> 4;
        cpa16(sbase + (OQ + d * QS + i8 * 8) * 2, qp + (long)d * NQ + i0 + i8 * 8);
    }
    #pragma unroll
    for (int r = 0; r < 8; r++) {
        int f = r * 256 + tid;
        int j8 = f & 31, d = f >> 5;
        cpa16(sbase + (OKk + d * KS + j8 * 8) * 2, kp + d * TLEN + j8 * 8);
        cpa16(sbase + (OV + d * VS + j8 * 8) * 2, vp + d * TLEN + j8 * 8);
    }
    CP_COMMIT();
    cp_wait<0>();
    __syncthreads();

    const int MB = wm * 32, NB = wn * 128;

    float acc[2][16][4];
    #pragma unroll
    for (int i = 0; i < 2; i++)
        #pragma unroll
        for (int j = 0; j < 16; j++)
            #pragma unroll
            for (int r = 0; r < 4; r++) acc[i][j][r] = 0.0f;

    #pragma unroll
    for (int ks = 0; ks < 4; ks++) {
        const int kof = ks * 16;
        uint32_t a[2][4];
        ldsm4t(a[0], sbase + (OQ + (kof + lhi8 + l8) * QS + MB + lq8) * 2);
        ldsm4t(a[1], sbase + (OQ + (kof + lhi8 + l8) * QS + MB + 16 + lq8) * 2);
        #pragma unroll
        for (int np = 0; np < 8; np++) {
            uint32_t bfr[4];
            ldsm4t(bfr, sbase + (OKk + (kof + l16) * KS + NB + np * 16 + lhi8) * 2);
            mma_f16(acc[0][np * 2],     a[0], bfr);
            mma_f16(acc[1][np * 2],     a[1], bfr);
            mma_f16(acc[0][np * 2 + 1], a[0], bfr + 2);
            mma_f16(acc[1][np * 2 + 1], a[1], bfr + 2);
        }
    }

    float* redm = red;
    float* reds = red + 256;
    float rmx[2][2], rsm[2][2], inv[2][2];
    #pragma unroll
    for (int mt = 0; mt < 2; mt++)
        #pragma unroll
        for (int u = 0; u < 2; u++) {
            float m = -INFINITY;
            #pragma unroll
            for (int nt = 0; nt < 16; nt++)
                m = fmaxf(m, fmaxf(acc[mt][nt][2 * u], acc[mt][nt][2 * u + 1]));
            m = fmaxf(m, __shfl_xor_sync(0xffffffffu, m, 1));
            m = fmaxf(m, __shfl_xor_sync(0xffffffffu, m, 2));
            if (t4 == 0) redm[wn * 128 + wm * 32 + mt * 16 + u * 8 + g] = m;
        }
    __syncthreads();
    #pragma unroll
    for (int mt = 0; mt < 2; mt++)
        #pragma unroll
        for (int u = 0; u < 2; u++) {
            int r = wm * 32 + mt * 16 + u * 8 + g;
            rmx[mt][u] = fmaxf(redm[r], redm[128 + r]);
            rsm[mt][u] = 0.0f;
        }

    #pragma unroll
    for (int mt = 0; mt < 2; mt++) {
        int row = MB + mt * 16 + g;
        #pragma unroll
        for (int nt = 0; nt < 16; nt++) {
            int col = NB + nt * 8 + 2 * t4;
            float e0 = __expf(acc[mt][nt][0] - rmx[mt][0]);
            float e1 = __expf(acc[mt][nt][1] - rmx[mt][0]);
            float e2 = __expf(acc[mt][nt][2] - rmx[mt][1]);
            float e3 = __expf(acc[mt][nt][3] - rmx[mt][1]);
            rsm[mt][0] += e0 + e1;
            rsm[mt][1] += e2 + e3;
            *(uint32_t*)&sh[OP + row * PS + col] = h2(e0, e1);
            *(uint32_t*)&sh[OP + (row + 8) * PS + col] = h2(e2, e3);
        }
    }
    #pragma unroll
    for (int mt = 0; mt < 2; mt++)
        #pragma unroll
        for (int u = 0; u < 2; u++) {
            float s = rsm[mt][u];
            s += __shfl_xor_sync(0xffffffffu, s, 1);
            s += __shfl_xor_sync(0xffffffffu, s, 2);
            if (t4 == 0) reds[wn * 128 + wm * 32 + mt * 16 + u * 8 + g] = s;
        }
    __syncthreads();
    #pragma unroll
    for (int mt = 0; mt < 2; mt++)
        #pragma unroll
        for (int u = 0; u < 2; u++) {
            int r = wm * 32 + mt * 16 + u * 8 + g;
            inv[mt][u] = 1.0f / (reds[r] + reds[128 + r]);
        }

    const int NB2 = wn * 32;
    float acco[2][4][4];
    #pragma unroll
    for (int i = 0; i < 2; i++)
        #pragma unroll
        for (int j = 0; j < 4; j++)
            #pragma unroll
            for (int r = 0; r < 4; r++) acco[i][j][r] = 0.0f;

    #pragma unroll
    for (int ks = 0; ks < 16; ks++) {
        const int kof = ks * 16;
        uint32_t a[2][4];
        ldsm4(a[0], sbase + (OP + (MB + l16) * PS + kof + lhi8) * 2);
        ldsm4(a[1], sbase + (OP + (MB + 16 + l16) * PS + kof + lhi8) * 2);
        #pragma unroll
        for (int np = 0; np < 2; np++) {
            uint32_t bfr[4];
            ldsm4(bfr, sbase + (OV + (NB2 + np * 16 + lhi8 + l8) * VS + kof + lq8) * 2);
            mma_f16(acco[0][np * 2],     a[0], bfr);
            mma_f16(acco[1][np * 2],     a[1], bfr);
            mma_f16(acco[0][np * 2 + 1], a[0], bfr + 2);
            mma_f16(acco[1][np * 2 + 1], a[1], bfr + 2);
        }
    }

    __half* op = out + ((long)b * NQ + i0) * HID + h * DHEAD;
    #pragma unroll
    for (int mt = 0; mt < 2; mt++) {
        int rl = MB + mt * 16 + g;
        #pragma unroll
        for (int nt = 0; nt < 4; nt++) {
            int d = NB2 + nt * 8 + 2 * t4;
            *(uint32_t*)(op + (long)rl * HID + d) =
                h2(acco[mt][nt][0] * inv[mt][0], acco[mt][nt][1] * inv[mt][0]);
            *(uint32_t*)(op + (long)(rl + 8) * HID + d) =
                h2(acco[mt][nt][2] * inv[mt][1], acco[mt][nt][3] * inv[mt][1]);
        }
    }
}

// ================= launch =================
extern "C" void kernel_launch(void* const* d_in, const int* in_sizes, int n_in,
                              void* d_out, int out_size)
{
    const float* x    = (const float*)d_in[0];
    const float* ctx  = (const float*)d_in[1];
    const float* Wq   = (const float*)d_in[2];
    const float* Wkv  = (const float*)d_in[3];
    const float* Wout = (const float*)d_in[4];
    const float* bout = (const float*)d_in[5];
    float* y = (float*)d_out;

    __half *xh, *ctxh, *Wqh, *Wkvh, *Wouth, *q, *kv, *outb;
    cudaGetSymbolAddress((void**)&xh,    g_xh);
    cudaGetSymbolAddress((void**)&ctxh,  g_ctxh);
    cudaGetSymbolAddress((void**)&Wqh,   g_Wqh);
    cudaGetSymbolAddress((void**)&Wkvh,  g_Wkvh);
    cudaGetSymbolAddress((void**)&Wouth, g_Wouth);
    cudaGetSymbolAddress((void**)&q,     g_q);
    cudaGetSymbolAddress((void**)&kv,    g_kv);
    cudaGetSymbolAddress((void**)&outb,  g_out);

    constexpr int SM_B1 = 3 * (256 * 40 + 128 * 40) * 2;   // 92160
    constexpr int SM_B0 = 3 * (256 * 40 + 32 * 136) * 2;   // 87552

    cudaFuncSetAttribute((const void*)hgemm<0, __half>, cudaFuncAttributeMaxDynamicSharedMemorySize, SM_B0);
    cudaFuncSetAttribute((const void*)hgemm<1, __half>, cudaFuncAttributeMaxDynamicSharedMemorySize, SM_B1);
    cudaFuncSetAttribute((const void*)hgemm<1, float>,  cudaFuncAttributeMaxDynamicSharedMemorySize, SM_B1);
    cudaFuncSetAttribute((const void*)fused_attn,       cudaFuncAttributeMaxDynamicSharedMemorySize, FSM_BYTES);

    dim3 blk(256);

    // 0) fp32 -> fp16 conversions
    {
        long nx = (long)BATCH * CCH * NQ / 4;
        f2h_kernel<<<(int)((nx + 255) / 256), blk>>>((const float4*)x, (uint2*)xh, (int)nx);
        long nc = (long)BATCH * TLEN * CDIM / 4;
        f2h_kernel<<<(int)((nc + 255) / 256), blk>>>((const float4*)ctx, (uint2*)ctxh, (int)nc);
        int nq_ = HID * CCH / 4;
        f2h_kernel<<<(nq_ + 255) / 256, blk>>>((const float4*)Wq, (uint2*)Wqh, nq_);
        int nk = 2 * HID * CDIM / 4;
        f2h_kernel<<<(nk + 255) / 256, blk>>>((const float4*)Wkv, (uint2*)Wkvh, nk);
        int no = CCH * HID / 4;
        f2h_kernel<<<(no + 255) / 256, blk>>>((const float4*)Wout, (uint2*)Wouth, no);
    }

    // 1) q = 0.125 * Wq @ x    (M=512,N=4096,K=512)/batch; B=xh[c][n] n-contig
    hgemm<0, __half><<<dim3(NQ / 128, CCH / 256, BATCH), blk, SM_B0>>>(
        Wqh, xh, q, nullptr, CCH, NQ, NQ, CCH,
        (long)CCH * NQ, (long)HID * NQ, 0.125f);

    // 2) kv = Wkv @ ctx^T      (M=1024,N=256,K=768)/batch; B=ctxh[t][c] k-contig
    hgemm<1, __half><<<dim3(TLEN / 128, (2 * HID) / 256, BATCH), blk, SM_B1>>>(
        Wkvh, ctxh, kv, nullptr, CDIM, CDIM, TLEN, CDIM,
        (long)TLEN * CDIM, (long)2 * HID * TLEN, 1.0f);

    // 3) fused attention -> outb [b][i][hd] fp16
    fused_attn<<<dim3(NQ / 128, BATCH * NHEAD), blk, FSM_BYTES>>>(q, kv, outb);

    // 4) y = Wout @ out + bout (M=512,N=4096,K=512)/batch; B=outb[i][hd] k-contig
    hgemm<1, float><<<dim3(NQ / 128, CCH / 256, BATCH), blk, SM_B1>>>(
        Wouth, outb, y, bout, HID, HID, NQ, HID,
        (long)NQ * HID, (long)CCH * NQ, 1.0f);
}

// round 9
// speedup vs baseline: 1.8886x; 1.8886x over previous
#include <cuda_runtime.h>
#include <cuda_fp16.h>
#include <cstdint>
#include <math.h>

// ---------------- problem dims ----------------
#define BATCH 8
#define CCH   512
#define NQ    4096
#define TLEN  256
#define CDIM  768
#define HID   512
#define NHEAD 8
#define DHEAD 64

// ---------------- scratch ----------------
__device__ __half g_xh  [(long)BATCH * CCH * NQ];
__device__ __half g_ctxh[(long)BATCH * TLEN * CDIM];
__device__ __half g_Wqh [HID * CCH];
__device__ __half g_Wkvh[2 * HID * CDIM];
__device__ __half g_Wouth[CCH * HID];
__device__ __half g_q   [(long)BATCH * HID * NQ];        // [b][o][i]
__device__ __half g_kv  [(long)BATCH * 2 * HID * TLEN];  // [b][o][t]
__device__ __half g_out [(long)BATCH * NQ * HID];        // [b][i][hd]

__device__ __forceinline__ uint32_t smem_u32(const void* p) {
    uint32_t a;
    asm("{ .reg .u64 t; cvta.to.shared.u64 t, %1; cvt.u32.u64 %0, t; }" : "=r"(a) : "l"(p));
    return a;
}
__device__ __forceinline__ uint32_t h2(float a, float b) {
    __half2 h = __floats2half2_rn(a, b);
    return *(uint32_t*)&h;
}
__device__ __forceinline__ void cpa16(uint32_t dst, const void* src) {
    asm volatile("cp.async.cg.shared.global [%0], [%1], 16;" :: "r"(dst), "l"(src));
}
#define CP_COMMIT() asm volatile("cp.async.commit_group;" ::: "memory")
template<int N> __device__ __forceinline__ void cp_wait() {
    asm volatile("cp.async.wait_group %0;" :: "n"(N) : "memory");
}
__device__ __forceinline__ void ldsm4(uint32_t* r, uint32_t addr) {
    asm volatile("ldmatrix.sync.aligned.m8n8.x4.shared.b16 {%0,%1,%2,%3}, [%4];"
                 : "=r"(r[0]), "=r"(r[1]), "=r"(r[2]), "=r"(r[3]) : "r"(addr));
}
__device__ __forceinline__ void ldsm4t(uint32_t* r, uint32_t addr) {
    asm volatile("ldmatrix.sync.aligned.m8n8.x4.trans.shared.b16 {%0,%1,%2,%3}, [%4];"
                 : "=r"(r[0]), "=r"(r[1]), "=r"(r[2]), "=r"(r[3]) : "r"(addr));
}
__device__ __forceinline__ void mma_f16(float* d, const uint32_t* a, const uint32_t* b) {
    asm volatile(
        "mma.sync.aligned.m16n8k16.row.col.f32.f16.f16.f32 "
        "{%0,%1,%2,%3}, {%4,%5,%6,%7}, {%8,%9}, {%0,%1,%2,%3};"
        : "+f"(d[0]), "+f"(d[1]), "+f"(d[2]), "+f"(d[3])
        : "r"(a[0]), "r"(a[1]), "r"(a[2]), "r"(a[3]), "r"(b[0]), "r"(b[1]));
}

// ---------------- fp32 -> fp16 conversion ----------------
__global__ __launch_bounds__(256) void f2h_kernel(
    const float4* __restrict__ in, uint2* __restrict__ out, int n4)
{
    int i = blockIdx.x * 256 + threadIdx.x;
    if (i < n4) {
        float4 v = in[i];
        out[i] = make_uint2(h2(v.x, v.y), h2(v.z, v.w));
    }
}

// =====================================================================
// fp16 mma GEMM, CTA tile 128x128, warp tile 32x64 (4x2 warps), BK=32,
// 4-stage cp.async, 2 CTAs/SM.
//   C[z][m][n] = alpha * A[m][k] * B(k,n) (+ bias[m])
// A[m][k] k-contig. BDIR=1: B[n][k] k-contig. BDIR=0: B[k][n] n-contig.
// =====================================================================
template<int BDIR, typename CT>
__global__ __launch_bounds__(256, 2) void hgemm(
    const __half* __restrict__ A, const __half* __restrict__ B,
    CT* __restrict__ C, const float* __restrict__ bias,
    int lda, int ldb, int ldc, int kTotal,
    long sB1, long sC1, float alpha)
{
    constexpr int BM = 128, BN = 128, BK = 32;
    constexpr int AS = BK + 8;                      // 40 halves
    constexpr int BS = BDIR ? (BK + 8) : (BN + 8);  // 40 or 136
    constexpr int BROWS = BDIR ? BN : BK;
    constexpr int ASTG = BM * AS;
    constexpr int BSTG = BROWS * BS;
    constexpr int NSTAGE = 4;

    extern __shared__ __half sm[];
    __half* Asm = sm;
    __half* Bsm = sm + NSTAGE * ASTG;

    const int z = blockIdx.z;
    B += (long)z * sB1;
    C += (long)z * sC1;

    const int tid = threadIdx.x;
    const int wid = tid >> 5, lane = tid & 31;
    const int wm = wid & 3, wn = wid >> 2;
    const int g = lane >> 2, t4 = lane & 3;
    const int l8 = lane & 7, l16 = lane & 15;
    const int lhi8 = (lane >> 4) << 3;
    const int lq8 = ((lane >> 3) & 1) << 3;

    const int m0 = blockIdx.y * BM;
    const int n0 = blockIdx.x * BN;
    const int mb = wm * 32, nb = wn * 64;

    const uint32_t Aaddr = smem_u32(Asm);
    const uint32_t Baddr = smem_u32(Bsm);

    float acc[2][8][4];
    #pragma unroll
    for (int i = 0; i < 2; i++)
        #pragma unroll
        for (int j = 0; j < 8; j++)
            #pragma unroll
            for (int r = 0; r < 4; r++) acc[i][j][r] = 0.0f;

    auto LOADS = [&](int s, int k0) {
        uint32_t ab = Aaddr + s * (ASTG * 2);
        uint32_t bb = Baddr + s * (BSTG * 2);
        #pragma unroll
        for (int r = 0; r < 2; r++) {
            int f = r * 256 + tid;
            int k8 = f & 3, m = f >> 2;
            cpa16(ab + (m * AS + k8 * 8) * 2, A + (long)(m0 + m) * lda + k0 + k8 * 8);
        }
        #pragma unroll
        for (int r = 0; r < 2; r++) {
            int f = r * 256 + tid;
            if (BDIR) {
                int k8 = f & 3, n = f >> 2;
                cpa16(bb + (n * BS + k8 * 8) * 2, B + (long)(n0 + n) * ldb + k0 + k8 * 8);
            } else {
                int n8 = f & 15, kk = f >> 4;
                cpa16(bb + (kk * BS + n8 * 8) * 2, B + (long)(k0 + kk) * ldb + n0 + n8 * 8);
            }
        }
    };
    auto COMPUTE = [&](int s) {
        const uint32_t ab = Aaddr + s * (ASTG * 2);
        const uint32_t bb = Baddr + s * (BSTG * 2);
        #pragma unroll
        for (int ks = 0; ks < 2; ks++) {
            const int kof = ks * 16;
            uint32_t a[2][4];
            ldsm4(a[0], ab + ((mb + l16) * AS + kof + lhi8) * 2);
            ldsm4(a[1], ab + ((mb + 16 + l16) * AS + kof + lhi8) * 2);
            #pragma unroll
            for (int np = 0; np < 4; np++) {
                uint32_t b[4];
                if (BDIR)
                    ldsm4(b, bb + ((nb + np * 16 + lhi8 + l8) * BS + kof + lq8) * 2);
                else
                    ldsm4t(b, bb + ((kof + l16) * BS + nb + np * 16 + lhi8) * 2);
                mma_f16(acc[0][np * 2],     a[0], b);
                mma_f16(acc[1][np * 2],     a[1], b);
                mma_f16(acc[0][np * 2 + 1], a[0], b + 2);
                mma_f16(acc[1][np * 2 + 1], a[1], b + 2);
            }
        }
    };

    const int niter = kTotal / BK;
    LOADS(0, 0);
    CP_COMMIT();
    LOADS(1, BK);
    CP_COMMIT();
    LOADS(2, 2 * BK);
    CP_COMMIT();
    cp_wait<2>();
    __syncthreads();

    for (int it = 0; it < niter; it++) {
        COMPUTE(it & 3);
        if (it + 3 < niter) {
            LOADS((it + 3) & 3, (it + 3) * BK);
            CP_COMMIT();
            cp_wait<2>();
        } else if (it + 1 < niter) {
            cp_wait<0>();
        }
        if (it + 1 < niter) __syncthreads();
    }

    #pragma unroll
    for (int mt = 0; mt < 2; mt++) {
        int m = m0 + mb + mt * 16 + g;
        float bv0 = bias ? bias[m] : 0.0f;
        float bv1 = bias ? bias[m + 8] : 0.0f;
        #pragma unroll
        for (int nt = 0; nt < 8; nt++) {
            int n = n0 + nb + nt * 8 + t4 * 2;
            if (sizeof(CT) == 4) {
                *(float2*)((float*)C + (long)m * ldc + n) =
                    make_float2(acc[mt][nt][0] * alpha + bv0, acc[mt][nt][1] * alpha + bv0);
                *(float2*)((float*)C + (long)(m + 8) * ldc + n) =
                    make_float2(acc[mt][nt][2] * alpha + bv1, acc[mt][nt][3] * alpha + bv1);
            } else {
                *(uint32_t*)((__half*)C + (long)m * ldc + n) =
                    h2(acc[mt][nt][0] * alpha + bv0, acc[mt][nt][1] * alpha + bv0);
                *(uint32_t*)((__half*)C + (long)(m + 8) * ldc + n) =
                    h2(acc[mt][nt][2] * alpha + bv1, acc[mt][nt][3] * alpha + bv1);
            }
        }
    }
}

// =====================================================================
// Fused attention, 64-query tiles, 2 CTAs/SM.
// Per CTA: (b,h) x 64 queries. S warp grid 2x4 (tile 32x64),
// PV warp grid 2x4 (tile 32x16). Smem: Q[d64][i64]s72, K/V[d64][j256]s264,
// P[i64][j256]s264.  112.6 KB total.
// =====================================================================
#define QS 72
#define KS 264
#define VS 264
#define PS 264
#define OQ 0
#define OKk (OQ + 64 * QS)          // 4608
#define OV  (OKk + 64 * KS)         // 21504
#define OP  (OV + 64 * VS)          // 38400
#define FH_TOTAL (OP + 64 * PS)     // 55296 halves
#define RED_BYTES 2048
#define FSM_BYTES (FH_TOTAL * 2 + RED_BYTES)   // 112640

__global__ __launch_bounds__(256, 2) void fused_attn(
    const __half* __restrict__ q, const __half* __restrict__ kv,
    __half* __restrict__ out)
{
    extern __shared__ __align__(16) char smraw[];
    __half* sh = (__half*)smraw;
    float* red = (float*)(smraw + FH_TOTAL * 2);

    const int z = blockIdx.y;            // b*8 + h
    const int b = z >> 3, h = z & 7;
    const int i0 = blockIdx.x * 64;
    const int tid = threadIdx.x;
    const int wid = tid >> 5, lane = tid & 31;
    const int wm = wid & 1, wn = wid >> 1;   // 2 x 4
    const int g = lane >> 2, t4 = lane & 3;
    const int l8 = lane & 7, l16 = lane & 15;
    const int lhi8 = (lane >> 4) << 3;
    const int lq8 = ((lane >> 3) & 1) << 3;

    const __half* qp = q + (long)(b * HID + h * DHEAD) * NQ;
    const __half* kp = kv + (long)(b * 2 * HID + h * DHEAD) * TLEN;
    const __half* vp = kp + (long)HID * TLEN;

    const uint32_t sbase = smem_u32(sh);

    // ---- async loads: Q 64x64, K,V 64x256 ----
    #pragma unroll
    for (int r = 0; r < 2; r++) {
        int f = r * 256 + tid;
        int i8 = f & 7, d = f >> 3;
        cpa16(sbase + (OQ + d * QS + i8 * 8) * 2, qp + (long)d * NQ + i0 + i8 * 8);
    }
    #pragma unroll
    for (int r = 0; r < 8; r++) {
        int f = r * 256 + tid;
        int j8 = f & 31, d = f >> 5;
        cpa16(sbase + (OKk + d * KS + j8 * 8) * 2, kp + d * TLEN + j8 * 8);
        cpa16(sbase + (OV + d * VS + j8 * 8) * 2, vp + d * TLEN + j8 * 8);
    }
    CP_COMMIT();
    cp_wait<0>();
    __syncthreads();

    const int MB = wm * 32, NB = wn * 64;

    // ---- S = Q^T K : warp tile 32 x 64 ----
    float acc[2][8][4];
    #pragma unroll
    for (int i = 0; i < 2; i++)
        #pragma unroll
        for (int j = 0; j < 8; j++)
            #pragma unroll
            for (int r = 0; r < 4; r++) acc[i][j][r] = 0.0f;

    #pragma unroll
    for (int ks = 0; ks < 4; ks++) {
        const int kof = ks * 16;
        uint32_t a[2][4];
        ldsm4t(a[0], sbase + (OQ + (kof + lhi8 + l8) * QS + MB + lq8) * 2);
        ldsm4t(a[1], sbase + (OQ + (kof + lhi8 + l8) * QS + MB + 16 + lq8) * 2);
        #pragma unroll
        for (int np = 0; np < 4; np++) {
            uint32_t bfr[4];
            ldsm4t(bfr, sbase + (OKk + (kof + l16) * KS + NB + np * 16 + lhi8) * 2);
            mma_f16(acc[0][np * 2],     a[0], bfr);
            mma_f16(acc[1][np * 2],     a[1], bfr);
            mma_f16(acc[0][np * 2 + 1], a[0], bfr + 2);
            mma_f16(acc[1][np * 2 + 1], a[1], bfr + 2);
        }
    }

    // ---- softmax: row max across 4 wn groups ----
    float* redm = red;          // [4][64]
    float* reds = red + 256;    // [4][64]
    float rmx[2][2], rsm[2][2], inv[2][2];
    #pragma unroll
    for (int mt = 0; mt < 2; mt++)
        #pragma unroll
        for (int u = 0; u < 2; u++) {
            float m = -INFINITY;
            #pragma unroll
            for (int nt = 0; nt < 8; nt++)
                m = fmaxf(m, fmaxf(acc[mt][nt][2 * u], acc[mt][nt][2 * u + 1]));
            m = fmaxf(m, __shfl_xor_sync(0xffffffffu, m, 1));
            m = fmaxf(m, __shfl_xor_sync(0xffffffffu, m, 2));
            if (t4 == 0) redm[wn * 64 + wm * 32 + mt * 16 + u * 8 + g] = m;
        }
    __syncthreads();
    #pragma unroll
    for (int mt = 0; mt < 2; mt++)
        #pragma unroll
        for (int u = 0; u < 2; u++) {
            int r = wm * 32 + mt * 16 + u * 8 + g;
            rmx[mt][u] = fmaxf(fmaxf(redm[r], redm[64 + r]),
                               fmaxf(redm[128 + r], redm[192 + r]));
            rsm[mt][u] = 0.0f;
        }

    // ---- exp, row-sum, stage P (fp16, unnormalized) ----
    #pragma unroll
    for (int mt = 0; mt < 2; mt++) {
        int row = MB + mt * 16 + g;
        #pragma unroll
        for (int nt = 0; nt < 8; nt++) {
            int col = NB + nt * 8 + 2 * t4;
            float e0 = __expf(acc[mt][nt][0] - rmx[mt][0]);
            float e1 = __expf(acc[mt][nt][1] - rmx[mt][0]);
            float e2 = __expf(acc[mt][nt][2] - rmx[mt][1]);
            float e3 = __expf(acc[mt][nt][3] - rmx[mt][1]);
            rsm[mt][0] += e0 + e1;
            rsm[mt][1] += e2 + e3;
            *(uint32_t*)&sh[OP + row * PS + col] = h2(e0, e1);
            *(uint32_t*)&sh[OP + (row + 8) * PS + col] = h2(e2, e3);
        }
    }
    #pragma unroll
    for (int mt = 0; mt < 2; mt++)
        #pragma unroll
        for (int u = 0; u < 2; u++) {
            float s = rsm[mt][u];
            s += __shfl_xor_sync(0xffffffffu, s, 1);
            s += __shfl_xor_sync(0xffffffffu, s, 2);
            if (t4 == 0) reds[wn * 64 + wm * 32 + mt * 16 + u * 8 + g] = s;
        }
    __syncthreads();
    #pragma unroll
    for (int mt = 0; mt < 2; mt++)
        #pragma unroll
        for (int u = 0; u < 2; u++) {
            int r = wm * 32 + mt * 16 + u * 8 + g;
            inv[mt][u] = 1.0f / (reds[r] + reds[64 + r] + reds[128 + r] + reds[192 + r]);
        }

    // ---- O = P V : warp tile 32 x 16 over d ----
    const int NB2 = wn * 16;
    float acco[2][2][4];
    #pragma unroll
    for (int i = 0; i < 2; i++)
        #pragma unroll
        for (int j = 0; j < 2; j++)
            #pragma unroll
            for (int r = 0; r < 4; r++) acco[i][j][r] = 0.0f;

    #pragma unroll
    for (int ks = 0; ks < 16; ks++) {
        const int kof = ks * 16;
        uint32_t a[2][4];
        ldsm4(a[0], sbase + (OP + (MB + l16) * PS + kof + lhi8) * 2);
        ldsm4(a[1], sbase + (OP + (MB + 16 + l16) * PS + kof + lhi8) * 2);
        uint32_t bfr[4];
        ldsm4(bfr, sbase + (OV + (NB2 + lhi8 + l8) * VS + kof + lq8) * 2);
        mma_f16(acco[0][0], a[0], bfr);
        mma_f16(acco[1][0], a[1], bfr);
        mma_f16(acco[0][1], a[0], bfr + 2);
        mma_f16(acco[1][1], a[1], bfr + 2);
    }

    // ---- store O[b][i0+i][h*64+d] scaled ----
    __half* op = out + ((long)b * NQ + i0) * HID + h * DHEAD;
    #pragma unroll
    for (int mt = 0; mt < 2; mt++) {
        int rl = MB + mt * 16 + g;
        #pragma unroll
        for (int nt = 0; nt < 2; nt++) {
            int d = NB2 + nt * 8 + 2 * t4;
            *(uint32_t*)(op + (long)rl * HID + d) =
                h2(acco[mt][nt][0] * inv[mt][0], acco[mt][nt][1] * inv[mt][0]);
            *(uint32_t*)(op + (long)(rl + 8) * HID + d) =
                h2(acco[mt][nt][2] * inv[mt][1], acco[mt][nt][3] * inv[mt][1]);
        }
    }
}

// ================= launch =================
extern "C" void kernel_launch(void* const* d_in, const int* in_sizes, int n_in,
                              void* d_out, int out_size)
{
    const float* x    = (const float*)d_in[0];
    const float* ctx  = (const float*)d_in[1];
    const float* Wq   = (const float*)d_in[2];
    const float* Wkv  = (const float*)d_in[3];
    const float* Wout = (const float*)d_in[4];
    const float* bout = (const float*)d_in[5];
    float* y = (float*)d_out;

    __half *xh, *ctxh, *Wqh, *Wkvh, *Wouth, *q, *kv, *outb;
    cudaGetSymbolAddress((void**)&xh,    g_xh);
    cudaGetSymbolAddress((void**)&ctxh,  g_ctxh);
    cudaGetSymbolAddress((void**)&Wqh,   g_Wqh);
    cudaGetSymbolAddress((void**)&Wkvh,  g_Wkvh);
    cudaGetSymbolAddress((void**)&Wouth, g_Wouth);
    cudaGetSymbolAddress((void**)&q,     g_q);
    cudaGetSymbolAddress((void**)&kv,    g_kv);
    cudaGetSymbolAddress((void**)&outb,  g_out);

    constexpr int SM_B1 = 4 * (128 * 40 + 128 * 40) * 2;   // 81920
    constexpr int SM_B0 = 4 * (128 * 40 + 32 * 136) * 2;   // 75776

    cudaFuncSetAttribute((const void*)hgemm<0, __half>, cudaFuncAttributeMaxDynamicSharedMemorySize, SM_B0);
    cudaFuncSetAttribute((const void*)hgemm<1, __half>, cudaFuncAttributeMaxDynamicSharedMemorySize, SM_B1);
    cudaFuncSetAttribute((const void*)hgemm<1, float>,  cudaFuncAttributeMaxDynamicSharedMemorySize, SM_B1);
    cudaFuncSetAttribute((const void*)fused_attn,       cudaFuncAttributeMaxDynamicSharedMemorySize, FSM_BYTES);

    dim3 blk(256);

    // 0) fp32 -> fp16 conversions
    {
        long nx = (long)BATCH * CCH * NQ / 4;
        f2h_kernel<<<(int)((nx + 255) / 256), blk>>>((const float4*)x, (uint2*)xh, (int)nx);
        long nc = (long)BATCH * TLEN * CDIM / 4;
        f2h_kernel<<<(int)((nc + 255) / 256), blk>>>((const float4*)ctx, (uint2*)ctxh, (int)nc);
        int nq_ = HID * CCH / 4;
        f2h_kernel<<<(nq_ + 255) / 256, blk>>>((const float4*)Wq, (uint2*)Wqh, nq_);
        int nk = 2 * HID * CDIM / 4;
        f2h_kernel<<<(nk + 255) / 256, blk>>>((const float4*)Wkv, (uint2*)Wkvh, nk);
        int no = CCH * HID / 4;
        f2h_kernel<<<(no + 255) / 256, blk>>>((const float4*)Wout, (uint2*)Wouth, no);
    }

    // 1) q = 0.125 * Wq @ x    (M=512,N=4096,K=512)/batch; B=xh[c][n] n-contig
    hgemm<0, __half><<<dim3(NQ / 128, CCH / 128, BATCH), blk, SM_B0>>>(
        Wqh, xh, q, nullptr, CCH, NQ, NQ, CCH,
        (long)CCH * NQ, (long)HID * NQ, 0.125f);

    // 2) kv = Wkv @ ctx^T      (M=1024,N=256,K=768)/batch; B=ctxh[t][c] k-contig
    hgemm<1, __half><<<dim3(TLEN / 128, (2 * HID) / 128, BATCH), blk, SM_B1>>>(
        Wkvh, ctxh, kv, nullptr, CDIM, CDIM, TLEN, CDIM,
        (long)TLEN * CDIM, (long)2 * HID * TLEN, 1.0f);

    // 3) fused attention -> outb [b][i][hd] fp16  (64-query tiles, 2 CTAs/SM)
    fused_attn<<<dim3(NQ / 64, BATCH * NHEAD), blk, FSM_BYTES>>>(q, kv, outb);

    // 4) y = Wout @ out + bout (M=512,N=4096,K=512)/batch; B=outb[i][hd] k-contig
    hgemm<1, float><<<dim3(NQ / 128, CCH / 128, BATCH), blk, SM_B1>>>(
        Wouth, outb, y, bout, HID, HID, NQ, HID,
        (long)NQ * HID, (long)CCH * NQ, 1.0f);
}